// round 7
// baseline (speedup 1.0000x reference)
#include <cuda_runtime.h>
#include <cuda_bf16.h>

#define BATCH 4
#define NTOK  4096
#define CIN   512
#define DQK   64
#define DV    256
#define MTOT  (BATCH * NTOK)   // 16384

// Scratch (device globals; no runtime allocation allowed)
__device__ __align__(16) __nv_bfloat16 g_fb[MTOT * DQK];     // keys    bf16
__device__ __align__(16) __nv_bfloat16 g_gb[MTOT * DQK];     // queries bf16
__device__ __align__(16) __nv_bfloat16 g_hb[MTOT * DV];      // values  bf16
__device__ __align__(16) __nv_bfloat16 g_ob[MTOT * DV];      // attn out bf16

// ---------------------------------------------------------------------------
// PTX helpers
// ---------------------------------------------------------------------------
__device__ __forceinline__ unsigned smaddr(const void* p) {
    return (unsigned)__cvta_generic_to_shared(p);
}
__device__ __forceinline__ void ldsm_x4(unsigned a, unsigned* r) {
    asm volatile("ldmatrix.sync.aligned.m8n8.x4.shared.b16 {%0,%1,%2,%3},[%4];"
                 : "=r"(r[0]), "=r"(r[1]), "=r"(r[2]), "=r"(r[3]) : "r"(a));
}
__device__ __forceinline__ void ldsm_x4_trans(unsigned a, unsigned* r) {
    asm volatile("ldmatrix.sync.aligned.m8n8.x4.trans.shared.b16 {%0,%1,%2,%3},[%4];"
                 : "=r"(r[0]), "=r"(r[1]), "=r"(r[2]), "=r"(r[3]) : "r"(a));
}
__device__ __forceinline__ void mma16816(float* c, const unsigned* a, const unsigned* b) {
    asm volatile(
        "mma.sync.aligned.m16n8k16.row.col.f32.bf16.bf16.f32 "
        "{%0,%1,%2,%3},{%4,%5,%6,%7},{%8,%9},{%0,%1,%2,%3};"
        : "+f"(c[0]), "+f"(c[1]), "+f"(c[2]), "+f"(c[3])
        : "r"(a[0]), "r"(a[1]), "r"(a[2]), "r"(a[3]), "r"(b[0]), "r"(b[1]));
}
__device__ __forceinline__ void cp_async16(void* smem_dst, const void* gmem_src) {
    asm volatile("cp.async.cg.shared.global [%0], [%1], 16;"
                 :: "r"(smaddr(smem_dst)), "l"(gmem_src));
}
__device__ __forceinline__ unsigned packbf(float a, float b) {
    __nv_bfloat162 t = __floats2bfloat162_rn(a, b);
    return *(unsigned*)&t;
}

// ---------------------------------------------------------------------------
// Kernel 1: projection GEMM, double-buffered, advancing-pointer loads.
// grid=(3,128), BM=128 BN=128 BK=32, 8 warps.
// ---------------------------------------------------------------------------
#define AP 40
#define BPP 136
#define PROJ_NIT (CIN / 32)   // 16

__global__ __launch_bounds__(256) void proj_gemm(
    const float* __restrict__ x,
    const float* __restrict__ Wf, const float* __restrict__ Wg,
    const float* __restrict__ Wh,
    const float* __restrict__ bf, const float* __restrict__ bg,
    const float* __restrict__ bh)
{
    __shared__ __nv_bfloat16 As[2][128 * AP];
    __shared__ __nv_bfloat16 Bs[2][32 * BPP];

    const int tid  = threadIdx.x;
    const int lane = tid & 31;
    const int w    = tid >> 5;
    const int m0   = blockIdx.y * 128;
    const int n0   = blockIdx.x * 128;
    const int mw   = (w >> 1) * 32;
    const int nw   = (w & 1) * 64;

    // Advancing source pointers (no per-iter address math)
    const float* aptr[4];
    const float* bptr[4];
    int bstep[4];
    __nv_bfloat16* asd[4];
    __nv_bfloat16* bsd[4];
    #pragma unroll
    for (int it = 0; it < 4; ++it) {
        int idx = tid + 256 * it;
        int ar = idx >> 3, ac = (idx & 7) * 4;
        aptr[it] = x + (size_t)(m0 + ar) * CIN + ac;
        asd[it]  = (__nv_bfloat16*)0 + (ar * AP + ac);   // offset only
        int br = idx >> 5, bc = (idx & 31) * 4;
        int nn = n0 + bc;
        const float* base; int ld;
        if (nn < 64)       { base = Wf + nn;         ld = DQK; }
        else if (nn < 128) { base = Wg + (nn - 64);  ld = DQK; }
        else               { base = Wh + (nn - 128); ld = DV;  }
        bptr[it]  = base + (size_t)br * ld;
        bstep[it] = 32 * ld;
        bsd[it]   = (__nv_bfloat16*)0 + (br * BPP + bc);
    }

    float4 aR[4], bR[4];
    auto ldg_tiles = [&]() {
        #pragma unroll
        for (int it = 0; it < 4; ++it) { aR[it] = *(const float4*)aptr[it]; aptr[it] += 32; }
        #pragma unroll
        for (int it = 0; it < 4; ++it) { bR[it] = *(const float4*)bptr[it]; bptr[it] += bstep[it]; }
    };
    auto sts_tiles = [&](int buf) {
        #pragma unroll
        for (int it = 0; it < 4; ++it) {
            __nv_bfloat16* d = As[buf] + (asd[it] - (__nv_bfloat16*)0);
            *(__nv_bfloat162*)&d[0] = __floats2bfloat162_rn(aR[it].x, aR[it].y);
            *(__nv_bfloat162*)&d[2] = __floats2bfloat162_rn(aR[it].z, aR[it].w);
        }
        #pragma unroll
        for (int it = 0; it < 4; ++it) {
            __nv_bfloat16* d = Bs[buf] + (bsd[it] - (__nv_bfloat16*)0);
            *(__nv_bfloat162*)&d[0] = __floats2bfloat162_rn(bR[it].x, bR[it].y);
            *(__nv_bfloat162*)&d[2] = __floats2bfloat162_rn(bR[it].z, bR[it].w);
        }
    };

    float acc[2][8][4];
    #pragma unroll
    for (int m = 0; m < 2; ++m)
        #pragma unroll
        for (int t = 0; t < 8; ++t)
            #pragma unroll
            for (int e = 0; e < 4; ++e) acc[m][t][e] = 0.0f;

    const int lrow = (lane & 7) + 8 * ((lane >> 3) & 1);
    const int lcol = 8 * (lane >> 4);

    ldg_tiles();
    sts_tiles(0);

    for (int k = 0; k < PROJ_NIT; ++k) {
        const int buf = k & 1;
        if (k + 1 < PROJ_NIT) ldg_tiles();
        __syncthreads();

        unsigned af[2][2][4];
        #pragma unroll
        for (int m = 0; m < 2; ++m)
            #pragma unroll
            for (int kb = 0; kb < 2; ++kb)
                ldsm_x4(smaddr(&As[buf][(mw + m * 16 + lrow) * AP + kb * 16 + lcol]),
                        af[m][kb]);
        #pragma unroll
        for (int kb = 0; kb < 2; ++kb) {
            #pragma unroll
            for (int j = 0; j < 4; ++j) {
                unsigned bv[4];
                ldsm_x4_trans(smaddr(&Bs[buf][(kb * 16 + lrow) * BPP + nw + 16 * j + lcol]), bv);
                #pragma unroll
                for (int m = 0; m < 2; ++m) {
                    mma16816(acc[m][2 * j + 0], af[m][kb], bv + 0);
                    mma16816(acc[m][2 * j + 1], af[m][kb], bv + 2);
                }
            }
        }
        if (k + 1 < PROJ_NIT) sts_tiles(buf ^ 1);
    }

    const int gc = n0 + nw;
    __nv_bfloat16* out;
    const float* bias;
    int ldo, coff;
    if (gc < 64)        { out = g_fb; bias = bf; ldo = DQK; coff = 0; }
    else if (gc < 128)  { out = g_gb; bias = bg; ldo = DQK; coff = 64; }
    else                { out = g_hb; bias = bh; ldo = DV;  coff = 128; }

    const int crow = lane >> 2;
    const int ccol = 2 * (lane & 3);
    #pragma unroll
    for (int m = 0; m < 2; ++m) {
        int r1 = m0 + mw + m * 16 + crow;
        int r2 = r1 + 8;
        #pragma unroll
        for (int t = 0; t < 8; ++t) {
            int col = gc - coff + 8 * t + ccol;
            float b0 = bias[col], b1 = bias[col + 1];
            *(__nv_bfloat162*)&out[(size_t)r1 * ldo + col] =
                __floats2bfloat162_rn(acc[m][t][0] + b0, acc[m][t][1] + b1);
            *(__nv_bfloat162*)&out[(size_t)r2 * ldo + col] =
                __floats2bfloat162_rn(acc[m][t][2] + b0, acc[m][t][3] + b1);
        }
    }
}

// ---------------------------------------------------------------------------
// Kernel 2: flash attention. NEW warp split: 4 row-groups x 2 col-halves.
// Each warp: 32 query rows x 128 V-columns -> V ldsm traffic halved.
// Unnormalized exp softmax; l partials combined via smem at the end.
// ---------------------------------------------------------------------------
#define QP 72
#define VP 264

#define SM_Q  0          // 128*72*2 = 18432
#define SM_K  18432      // 2 x 9216
#define SM_V  36864      // 2 x 33792
#define SM_L  104448     // 2 x 128 floats = 1024
#define ATTN_SMEM_BYTES 105472

__global__ __launch_bounds__(256, 1) void attn_kernel()
{
    extern __shared__ char sm[];
    __nv_bfloat16* Qs = (__nv_bfloat16*)(sm + SM_Q);
    float* Lp = (float*)(sm + SM_L);   // [2][128] per-half row sums

    const int tid  = threadIdx.x;
    const int lane = tid & 31;
    const int w    = tid >> 5;
    const int rg   = w >> 1;    // 0..3: rows rg*32..+31
    const int hf   = w & 1;     // 0/1:  cols hf*128..+127
    const int b    = blockIdx.y;
    const int q0   = blockIdx.x * 128;

    const __nv_bfloat16* Fb = g_fb + (size_t)b * NTOK * DQK;
    const __nv_bfloat16* Gb = g_gb + (size_t)b * NTOK * DQK;
    const __nv_bfloat16* Hb = g_hb + (size_t)b * NTOK * DV;

    #pragma unroll
    for (int it = 0; it < 4; ++it) {
        int idx = tid + 256 * it;
        int r = idx >> 3, c = (idx & 7) * 8;
        *(uint4*)&Qs[r * QP + c] = *(const uint4*)&Gb[(size_t)(q0 + r) * DQK + c];
    }
    {
        __nv_bfloat16* Kd = (__nv_bfloat16*)(sm + SM_K);
        __nv_bfloat16* Vd = (__nv_bfloat16*)(sm + SM_V);
        #pragma unroll
        for (int it = 0; it < 2; ++it) {
            int idx = tid + 256 * it;
            int r = idx >> 3, c = (idx & 7) * 8;
            cp_async16(&Kd[r * QP + c], &Fb[(size_t)r * DQK + c]);
        }
        #pragma unroll
        for (int it = 0; it < 8; ++it) {
            int idx = tid + 256 * it;
            int r = idx >> 5, c = (idx & 31) * 8;
            cp_async16(&Vd[r * VP + c], &Hb[(size_t)r * DV + c]);
        }
        asm volatile("cp.async.commit_group;");
    }
    __syncthreads();

    // Q A-fragments: 2 row blocks (rg*32 + mblk*16), 4 k-blocks
    const int lrow   = (lane & 7) + 8 * ((lane >> 3) & 1);
    const int acolhi = 8 * (lane >> 4);
    unsigned qa[2][4][4];
    #pragma unroll
    for (int m = 0; m < 2; ++m)
        #pragma unroll
        for (int kb = 0; kb < 4; ++kb)
            ldsm_x4(smaddr(&Qs[(rg * 32 + m * 16 + lrow) * QP + kb * 16 + acolhi]),
                    qa[m][kb]);

    float oacc[2][16][4];
    #pragma unroll
    for (int m = 0; m < 2; ++m)
        #pragma unroll
        for (int t = 0; t < 16; ++t)
            #pragma unroll
            for (int e = 0; e < 4; ++e) oacc[m][t][e] = 0.0f;

    float lsum[2][2] = {{0.f, 0.f}, {0.f, 0.f}};   // [mblk][half-row]

    const int nbase = hf * 128;

    for (int kt = 0; kt < NTOK / 64; ++kt) {
        const int buf = kt & 1;

        if (kt < NTOK / 64 - 1) {
            const __nv_bfloat16* Fk = Fb + (size_t)(kt + 1) * 64 * DQK;
            const __nv_bfloat16* Hk = Hb + (size_t)(kt + 1) * 64 * DV;
            __nv_bfloat16* Kd = (__nv_bfloat16*)(sm + SM_K + (buf ^ 1) * 9216);
            __nv_bfloat16* Vd = (__nv_bfloat16*)(sm + SM_V + (buf ^ 1) * 33792);
            #pragma unroll
            for (int it = 0; it < 2; ++it) {
                int idx = tid + 256 * it;
                int r = idx >> 3, c = (idx & 7) * 8;
                cp_async16(&Kd[r * QP + c], &Fk[(size_t)r * DQK + c]);
            }
            #pragma unroll
            for (int it = 0; it < 8; ++it) {
                int idx = tid + 256 * it;
                int r = idx >> 5, c = (idx & 31) * 8;
                cp_async16(&Vd[r * VP + c], &Hk[(size_t)r * DV + c]);
            }
            asm volatile("cp.async.commit_group;");
            asm volatile("cp.async.wait_group 1;");
        } else {
            asm volatile("cp.async.wait_group 0;");
        }
        __syncthreads();

        const __nv_bfloat16* Ks = (const __nv_bfloat16*)(sm + SM_K + buf * 9216);
        const __nv_bfloat16* Vs = (const __nv_bfloat16*)(sm + SM_V + buf * 33792);

        // ---- S = Q @ K^T : 32 rows (2 blocks) x 64 keys per warp ----
        float sacc[2][8][4];
        #pragma unroll
        for (int m = 0; m < 2; ++m)
            #pragma unroll
            for (int t = 0; t < 8; ++t)
                #pragma unroll
                for (int e = 0; e < 4; ++e) sacc[m][t][e] = 0.0f;

        #pragma unroll
        for (int kb = 0; kb < 4; ++kb) {
            const int kc = kb * 16 + 8 * ((lane >> 3) & 1);
            #pragma unroll
            for (int h = 0; h < 4; ++h) {
                int nrow = h * 16 + (lane & 7) + 8 * (lane >> 4);
                unsigned bb[4];
                ldsm_x4(smaddr(&Ks[nrow * QP + kc]), bb);
                #pragma unroll
                for (int m = 0; m < 2; ++m) {
                    mma16816(sacc[m][2 * h + 0], qa[m][kb], bb + 0);
                    mma16816(sacc[m][2 * h + 1], qa[m][kb], bb + 2);
                }
            }
        }

        // ---- unnormalized exp + l accumulation + P pack ----
        unsigned pa[2][4][4];
        #pragma unroll
        for (int m = 0; m < 2; ++m) {
            #pragma unroll
            for (int j = 0; j < 8; ++j) {
                sacc[m][j][0] = __expf(sacc[m][j][0]);
                sacc[m][j][1] = __expf(sacc[m][j][1]);
                sacc[m][j][2] = __expf(sacc[m][j][2]);
                sacc[m][j][3] = __expf(sacc[m][j][3]);
                lsum[m][0] += sacc[m][j][0] + sacc[m][j][1];
                lsum[m][1] += sacc[m][j][2] + sacc[m][j][3];
            }
            #pragma unroll
            for (int kb = 0; kb < 4; ++kb) {
                pa[m][kb][0] = packbf(sacc[m][2 * kb][0],     sacc[m][2 * kb][1]);
                pa[m][kb][1] = packbf(sacc[m][2 * kb][2],     sacc[m][2 * kb][3]);
                pa[m][kb][2] = packbf(sacc[m][2 * kb + 1][0], sacc[m][2 * kb + 1][1]);
                pa[m][kb][3] = packbf(sacc[m][2 * kb + 1][2], sacc[m][2 * kb + 1][3]);
            }
        }

        // ---- O += P @ V : 32 rows x 128 cols (this warp's half) ----
        #pragma unroll
        for (int kb = 0; kb < 4; ++kb) {
            int vrow = kb * 16 + (lane & 7) + 8 * ((lane >> 3) & 1);
            #pragma unroll
            for (int j = 0; j < 8; ++j) {
                unsigned bv[4];
                ldsm_x4_trans(smaddr(&Vs[vrow * VP + nbase + 16 * j + 8 * (lane >> 4)]), bv);
                #pragma unroll
                for (int m = 0; m < 2; ++m) {
                    mma16816(oacc[m][2 * j + 0], pa[m][kb], bv + 0);
                    mma16816(oacc[m][2 * j + 1], pa[m][kb], bv + 2);
                }
            }
        }
        __syncthreads();
    }

    // Combine l across the two column-half warps via smem partials
    const int crow = lane >> 2;
    const int ccol = 2 * (lane & 3);
    #pragma unroll
    for (int m = 0; m < 2; ++m) {
        lsum[m][0] += __shfl_xor_sync(0xffffffffu, lsum[m][0], 1);
        lsum[m][0] += __shfl_xor_sync(0xffffffffu, lsum[m][0], 2);
        lsum[m][1] += __shfl_xor_sync(0xffffffffu, lsum[m][1], 1);
        lsum[m][1] += __shfl_xor_sync(0xffffffffu, lsum[m][1], 2);
    }
    if ((lane & 3) == 0) {
        #pragma unroll
        for (int m = 0; m < 2; ++m) {
            Lp[hf * 128 + rg * 32 + m * 16 + crow]     = lsum[m][0];
            Lp[hf * 128 + rg * 32 + m * 16 + crow + 8] = lsum[m][1];
        }
    }
    __syncthreads();

    // Epilogue: divide by total l, write O as bf16
    __nv_bfloat16* Op = g_ob + (size_t)b * NTOK * DV;
    #pragma unroll
    for (int m = 0; m < 2; ++m) {
        int lr1 = rg * 32 + m * 16 + crow;
        int lr2 = lr1 + 8;
        int r1 = q0 + lr1, r2 = q0 + lr2;
        float inv0 = 1.0f / (Lp[lr1] + Lp[128 + lr1]);
        float inv1 = 1.0f / (Lp[lr2] + Lp[128 + lr2]);
        #pragma unroll
        for (int t = 0; t < 16; ++t) {
            int c = nbase + 8 * t + ccol;
            *(__nv_bfloat162*)&Op[(size_t)r1 * DV + c] =
                __floats2bfloat162_rn(oacc[m][t][0] * inv0, oacc[m][t][1] * inv0);
            *(__nv_bfloat162*)&Op[(size_t)r2 * DV + c] =
                __floats2bfloat162_rn(oacc[m][t][2] * inv1, oacc[m][t][3] * inv1);
        }
    }
}

// ---------------------------------------------------------------------------
// Kernel 3: output projection, double-buffered pipeline (as R6).
// ---------------------------------------------------------------------------
#define OUT_NIT (DV / 32)    // 8

__global__ __launch_bounds__(256) void outproj_gemm(
    const float* __restrict__ x, const float* __restrict__ Wo,
    const float* __restrict__ bo, const float* __restrict__ gamma,
    float* __restrict__ out)
{
    __shared__ __nv_bfloat16 As[2][128 * AP];
    __shared__ __nv_bfloat16 Bs[2][32 * BPP];

    const int tid  = threadIdx.x;
    const int lane = tid & 31;
    const int w    = tid >> 5;
    const int m0   = blockIdx.y * 128;
    const int n0   = blockIdx.x * 128;
    const int mw   = (w >> 1) * 32;
    const int nw   = (w & 1) * 64;

    // Advancing pointers
    const __nv_bfloat16* agp[2];
    unsigned asmoff[2];
    const float* bgp[4];
    int bsoff[4];
    #pragma unroll
    for (int it = 0; it < 2; ++it) {
        int idx = tid + 256 * it;
        int r = idx >> 2, c = (idx & 3) * 8;
        agp[it]   = g_ob + (size_t)(m0 + r) * DV + c;
        asmoff[it] = r * AP + c;
    }
    #pragma unroll
    for (int it = 0; it < 4; ++it) {
        int idx = tid + 256 * it;
        int r = idx >> 5, c = (idx & 31) * 4;
        bgp[it]  = Wo + (size_t)r * CIN + n0 + c;
        bsoff[it] = r * BPP + c;
    }

    float4 bR[4];
    auto cp_a = [&](int buf) {
        #pragma unroll
        for (int it = 0; it < 2; ++it) {
            cp_async16(&As[buf][asmoff[it]], agp[it]);
            agp[it] += 32;
        }
        asm volatile("cp.async.commit_group;");
    };
    auto ldg_b = [&]() {
        #pragma unroll
        for (int it = 0; it < 4; ++it) { bR[it] = *(const float4*)bgp[it]; bgp[it] += 32 * CIN; }
    };
    auto sts_b = [&](int buf) {
        #pragma unroll
        for (int it = 0; it < 4; ++it) {
            __nv_bfloat16* d = &Bs[buf][bsoff[it]];
            *(__nv_bfloat162*)&d[0] = __floats2bfloat162_rn(bR[it].x, bR[it].y);
            *(__nv_bfloat162*)&d[2] = __floats2bfloat162_rn(bR[it].z, bR[it].w);
        }
    };

    float acc[2][8][4];
    #pragma unroll
    for (int m = 0; m < 2; ++m)
        #pragma unroll
        for (int t = 0; t < 8; ++t)
            #pragma unroll
            for (int e = 0; e < 4; ++e) acc[m][t][e] = 0.0f;

    const int lrow = (lane & 7) + 8 * ((lane >> 3) & 1);
    const int lcol = 8 * (lane >> 4);

    ldg_b();
    cp_a(0);
    sts_b(0);

    for (int k = 0; k < OUT_NIT; ++k) {
        const int buf = k & 1;
        if (k + 1 < OUT_NIT) {
            ldg_b();
            cp_a(buf ^ 1);
            asm volatile("cp.async.wait_group 1;");
        } else {
            asm volatile("cp.async.wait_group 0;");
        }
        __syncthreads();

        unsigned af[2][2][4];
        #pragma unroll
        for (int m = 0; m < 2; ++m)
            #pragma unroll
            for (int kb = 0; kb < 2; ++kb)
                ldsm_x4(smaddr(&As[buf][(mw + m * 16 + lrow) * AP + kb * 16 + lcol]),
                        af[m][kb]);
        #pragma unroll
        for (int kb = 0; kb < 2; ++kb) {
            #pragma unroll
            for (int j = 0; j < 4; ++j) {
                unsigned bv[4];
                ldsm_x4_trans(smaddr(&Bs[buf][(kb * 16 + lrow) * BPP + nw + 16 * j + lcol]), bv);
                #pragma unroll
                for (int m = 0; m < 2; ++m) {
                    mma16816(acc[m][2 * j + 0], af[m][kb], bv + 0);
                    mma16816(acc[m][2 * j + 1], af[m][kb], bv + 2);
                }
            }
        }
        if (k + 1 < OUT_NIT) sts_b(buf ^ 1);
    }

    const float ga = gamma[0];
    const int crow = lane >> 2;
    const int ccol = 2 * (lane & 3);
    #pragma unroll
    for (int m = 0; m < 2; ++m) {
        int r1 = m0 + mw + m * 16 + crow;
        int r2 = r1 + 8;
        #pragma unroll
        for (int t = 0; t < 8; ++t) {
            int col = n0 + nw + 8 * t + ccol;
            float b0 = bo[col], b1 = bo[col + 1];
            size_t i1 = (size_t)r1 * CIN + col;
            size_t i2 = (size_t)r2 * CIN + col;
            float2 x1 = *(const float2*)&x[i1];
            float2 x2 = *(const float2*)&x[i2];
            *(float2*)&out[i1] = make_float2(x1.x + ga * (acc[m][t][0] + b0),
                                             x1.y + ga * (acc[m][t][1] + b1));
            *(float2*)&out[i2] = make_float2(x2.x + ga * (acc[m][t][2] + b0),
                                             x2.y + ga * (acc[m][t][3] + b1));
        }
    }
}

// ---------------------------------------------------------------------------
extern "C" void kernel_launch(void* const* d_in, const int* in_sizes, int n_in,
                              void* d_out, int out_size)
{
    const float* x     = (const float*)d_in[0];
    const float* Wf    = (const float*)d_in[1];
    const float* bf    = (const float*)d_in[2];
    const float* Wg    = (const float*)d_in[3];
    const float* bg    = (const float*)d_in[4];
    const float* Wh    = (const float*)d_in[5];
    const float* bh    = (const float*)d_in[6];
    const float* Wo    = (const float*)d_in[7];
    const float* bo    = (const float*)d_in[8];
    const float* gamma = (const float*)d_in[9];
    float* out = (float*)d_out;

    cudaFuncSetAttribute(attn_kernel,
                         cudaFuncAttributeMaxDynamicSharedMemorySize,
                         ATTN_SMEM_BYTES);

    proj_gemm<<<dim3(3, 128), 256>>>(x, Wf, Wg, Wh, bf, bg, bh);
    attn_kernel<<<dim3(NTOK / 128, BATCH), 256, ATTN_SMEM_BYTES>>>();
    outproj_gemm<<<dim3(4, 128), 256>>>(x, Wo, bo, gamma, out);
}